// round 5
// baseline (speedup 1.0000x reference)
#include <cuda_runtime.h>
#include <cuda_bf16.h>

#define NBLOCKS 2048

// Scratch (no device allocs allowed).
__device__ double   g_part[NBLOCKS];
__device__ unsigned g_ticket;   // zero-initialized; reset to 0 by the closing block

// x: [rows, 128] fp32. One warp per row, 8 rows per iteration, grid-stride.
// Single fused kernel: in-block dtype probe, main accumulation, last-block finish.
__global__ void __launch_bounds__(256) mrl_fused_kernel(
    const float* __restrict__ x,
    const void* __restrict__ target,
    int rows, double inv_cnt,
    float* __restrict__ out)
{
    const int tid    = threadIdx.x;
    const int lane   = tid & 31;
    const int wid    = tid >> 5;
    const int gwarp  = (blockIdx.x * blockDim.x + tid) >> 5;
    const int nwarps = (gridDim.x * blockDim.x) >> 5;

    // ---- dtype probe (warp 0): int64 targets in [0,128) have all-zero odd words ----
    __shared__ int s_is64;
    const int* t32p = (const int*)target;
    if (wid == 0) {
        int nz = 0;
        #pragma unroll
        for (int j = 0; j < 4; j++)
            nz |= t32p[1 + 2 * (lane * 4 + j)];
        unsigned any = __ballot_sync(0xFFFFFFFFu, nz != 0);
        if (lane == 0) s_is64 = (any == 0u) ? 1 : 0;
    }
    __syncthreads();
    const int is64 = s_is64;

    const int*       t32 = (const int*)target;
    const long long* t64 = (const long long*)target;

    float a0 = 0.f, a1 = 0.f, a2 = 0.f, a3 = 0.f;

    int r = gwarp * 8;
    const int stride = nwarps * 8;

    // Main unrolled path: 8 full rows per iteration.
    for (; r + 7 < rows; r += stride) {
        int t0, t1, t2, t3, t4, t5, t6, t7;
        if (is64) {
            const longlong2 ta = *reinterpret_cast<const longlong2*>(t64 + r);
            const longlong2 tb = *reinterpret_cast<const longlong2*>(t64 + r + 2);
            const longlong2 tc = *reinterpret_cast<const longlong2*>(t64 + r + 4);
            const longlong2 td = *reinterpret_cast<const longlong2*>(t64 + r + 6);
            t0 = (int)ta.x; t1 = (int)ta.y; t2 = (int)tb.x; t3 = (int)tb.y;
            t4 = (int)tc.x; t5 = (int)tc.y; t6 = (int)td.x; t7 = (int)td.y;
        } else {
            const int4 ta = *reinterpret_cast<const int4*>(t32 + r);
            const int4 tb = *reinterpret_cast<const int4*>(t32 + r + 4);
            t0 = ta.x; t1 = ta.y; t2 = ta.z; t3 = ta.w;
            t4 = tb.x; t5 = tb.y; t6 = tb.z; t7 = tb.w;
        }

        const float* p = x + (size_t)r * 128;
        // Front-batched loads: 8 x LDG.128 per lane + 8 broadcast pos loads.
        const float4 v0 = reinterpret_cast<const float4*>(p        )[lane];
        const float4 v1 = reinterpret_cast<const float4*>(p + 128  )[lane];
        const float4 v2 = reinterpret_cast<const float4*>(p + 256  )[lane];
        const float4 v3 = reinterpret_cast<const float4*>(p + 384  )[lane];
        const float4 v4 = reinterpret_cast<const float4*>(p + 512  )[lane];
        const float4 v5 = reinterpret_cast<const float4*>(p + 640  )[lane];
        const float4 v6 = reinterpret_cast<const float4*>(p + 768  )[lane];
        const float4 v7 = reinterpret_cast<const float4*>(p + 896  )[lane];
        const float b0 = 0.5f - __ldg(p +       t0);
        const float b1 = 0.5f - __ldg(p + 128 + t1);
        const float b2 = 0.5f - __ldg(p + 256 + t2);
        const float b3 = 0.5f - __ldg(p + 384 + t3);
        const float b4 = 0.5f - __ldg(p + 512 + t4);
        const float b5 = 0.5f - __ldg(p + 640 + t5);
        const float b6 = 0.5f - __ldg(p + 768 + t6);
        const float b7 = 0.5f - __ldg(p + 896 + t7);

        a0 += fmaxf(v0.x + b0, 0.f) + fmaxf(v0.y + b0, 0.f)
            + fmaxf(v0.z + b0, 0.f) + fmaxf(v0.w + b0, 0.f);
        a1 += fmaxf(v1.x + b1, 0.f) + fmaxf(v1.y + b1, 0.f)
            + fmaxf(v1.z + b1, 0.f) + fmaxf(v1.w + b1, 0.f);
        a2 += fmaxf(v2.x + b2, 0.f) + fmaxf(v2.y + b2, 0.f)
            + fmaxf(v2.z + b2, 0.f) + fmaxf(v2.w + b2, 0.f);
        a3 += fmaxf(v3.x + b3, 0.f) + fmaxf(v3.y + b3, 0.f)
            + fmaxf(v3.z + b3, 0.f) + fmaxf(v3.w + b3, 0.f);
        a0 += fmaxf(v4.x + b4, 0.f) + fmaxf(v4.y + b4, 0.f)
            + fmaxf(v4.z + b4, 0.f) + fmaxf(v4.w + b4, 0.f);
        a1 += fmaxf(v5.x + b5, 0.f) + fmaxf(v5.y + b5, 0.f)
            + fmaxf(v5.z + b5, 0.f) + fmaxf(v5.w + b5, 0.f);
        a2 += fmaxf(v6.x + b6, 0.f) + fmaxf(v6.y + b6, 0.f)
            + fmaxf(v6.z + b6, 0.f) + fmaxf(v6.w + b6, 0.f);
        a3 += fmaxf(v7.x + b7, 0.f) + fmaxf(v7.y + b7, 0.f)
            + fmaxf(v7.z + b7, 0.f) + fmaxf(v7.w + b7, 0.f);
    }

    // Tail: remaining rows (none for the benchmark shape, kept for generality).
    for (; r < rows; r++) {
        const int tgt = is64 ? (int)t64[r] : t32[r];
        const float* p = x + (size_t)r * 128;
        const float4 v = reinterpret_cast<const float4*>(p)[lane];
        const float b  = 0.5f - __ldg(p + tgt);
        a0 += fmaxf(v.x + b, 0.f) + fmaxf(v.y + b, 0.f)
            + fmaxf(v.z + b, 0.f) + fmaxf(v.w + b, 0.f);
    }

    // Lane partials -> warp -> block.
    double d = (double)a0 + (double)a1 + (double)a2 + (double)a3;
    #pragma unroll
    for (int o = 16; o > 0; o >>= 1)
        d += __shfl_xor_sync(0xFFFFFFFFu, d, o);

    __shared__ double ws[8];
    if (lane == 0) ws[wid] = d;
    __syncthreads();

    __shared__ bool s_last;
    if (tid == 0) {
        double b = 0.0;
        #pragma unroll
        for (int i = 0; i < 8; i++) b += ws[i];
        g_part[blockIdx.x] = b;
        __threadfence();
        unsigned t = atomicAdd(&g_ticket, 1u);
        s_last = (t == (unsigned)gridDim.x - 1u);
    }
    __syncthreads();

    // ---- closing block: reduce all partials, finish, reset ticket ----
    if (s_last) {
        double s = 0.0;
        for (int i = tid; i < NBLOCKS; i += 256) s += g_part[i];
        #pragma unroll
        for (int o = 16; o > 0; o >>= 1)
            s += __shfl_xor_sync(0xFFFFFFFFu, s, o);
        if (lane == 0) ws[wid] = s;
        __syncthreads();
        if (tid == 0) {
            double b = 0.0;
            #pragma unroll
            for (int i = 0; i < 8; i++) b += ws[i];
            // Each row's target position contributed exactly max(0, 0.5) = 0.5.
            out[0] = (float)((b - 0.5 * (double)rows) * inv_cnt);
            g_ticket = 0;   // reset for the next (graph-replayed) call
        }
    }
}

extern "C" void kernel_launch(void* const* d_in, const int* in_sizes, int n_in,
                              void* d_out, int out_size)
{
    const float* x      = (const float*)d_in[0];   // [V, C, T] fp32
    const void*  target = d_in[1];                 // [V, C] int32 or int64 (auto-detected)
    float*       out    = (float*)d_out;

    const int T    = 128;
    const int rows = in_sizes[0] / T;              // V*C
    const double cnt = (double)rows * (double)(T - 1);

    mrl_fused_kernel<<<NBLOCKS, 256>>>(x, target, rows, 1.0 / cnt, out);
}

// round 8
// speedup vs baseline: 1.0404x; 1.0404x over previous
#include <cuda_runtime.h>
#include <cuda_bf16.h>

#define NBLOCKS 2048

// Scratch (no device allocs allowed).
__device__ double   g_part[NBLOCKS];
__device__ unsigned g_ticket;   // zero-init; reset to 0 by the closing block each call

// x: [rows, 128] fp32. One warp per row, 4 rows per iteration, grid-stride.
// The positive score x[r][tgt] is extracted from the already-loaded row data
// via SEL + shfl instead of a second (dependent) global load.
__global__ void __launch_bounds__(256, 4) mrl_fused_kernel(
    const float* __restrict__ x,
    const void* __restrict__ target,
    int rows, double inv_cnt,
    float* __restrict__ out)
{
    const int tid    = threadIdx.x;
    const int lane   = tid & 31;
    const int wid    = tid >> 5;
    const int gwarp  = (blockIdx.x * blockDim.x + tid) >> 5;
    const int nwarps = (gridDim.x * blockDim.x) >> 5;

    // ---- dtype probe (warp 0): int64 targets in [0,128) have all-zero odd words ----
    __shared__ int s_is64;
    const int* t32p = (const int*)target;
    if (wid == 0) {
        int nz = 0;
        #pragma unroll
        for (int j = 0; j < 4; j++)
            nz |= t32p[1 + 2 * (lane * 4 + j)];
        unsigned any = __ballot_sync(0xFFFFFFFFu, nz != 0);
        if (lane == 0) s_is64 = (any == 0u) ? 1 : 0;
    }
    __syncthreads();
    const int is64 = s_is64;

    const int*       t32 = (const int*)target;
    const long long* t64 = (const long long*)target;

    float a0 = 0.f, a1 = 0.f, a2 = 0.f, a3 = 0.f;

    int r = gwarp * 4;
    const int stride = nwarps * 4;

    for (; r + 3 < rows; r += stride) {
        int t0, t1, t2, t3;
        if (is64) {
            const longlong2 ta = *reinterpret_cast<const longlong2*>(t64 + r);
            const longlong2 tb = *reinterpret_cast<const longlong2*>(t64 + r + 2);
            t0 = (int)ta.x; t1 = (int)ta.y; t2 = (int)tb.x; t3 = (int)tb.y;
        } else {
            const int4 t = *reinterpret_cast<const int4*>(t32 + r);
            t0 = t.x; t1 = t.y; t2 = t.z; t3 = t.w;
        }

        const float* p = x + (size_t)r * 128;
        // Front-batched: 4 x LDG.128 per lane (the only x-loads in the loop).
        const float4 v0 = reinterpret_cast<const float4*>(p        )[lane];
        const float4 v1 = reinterpret_cast<const float4*>(p + 128  )[lane];
        const float4 v2 = reinterpret_cast<const float4*>(p + 256  )[lane];
        const float4 v3 = reinterpret_cast<const float4*>(p + 384  )[lane];

        // Extract the positive score from register data: each lane selects its
        // candidate component, then shfl broadcasts from the owning lane.
        float s0 = (t0 & 2) ? ((t0 & 1) ? v0.w : v0.z) : ((t0 & 1) ? v0.y : v0.x);
        float s1 = (t1 & 2) ? ((t1 & 1) ? v1.w : v1.z) : ((t1 & 1) ? v1.y : v1.x);
        float s2 = (t2 & 2) ? ((t2 & 1) ? v2.w : v2.z) : ((t2 & 1) ? v2.y : v2.x);
        float s3 = (t3 & 2) ? ((t3 & 1) ? v3.w : v3.z) : ((t3 & 1) ? v3.y : v3.x);
        const float b0 = 0.5f - __shfl_sync(0xFFFFFFFFu, s0, t0 >> 2);
        const float b1 = 0.5f - __shfl_sync(0xFFFFFFFFu, s1, t1 >> 2);
        const float b2 = 0.5f - __shfl_sync(0xFFFFFFFFu, s2, t2 >> 2);
        const float b3 = 0.5f - __shfl_sync(0xFFFFFFFFu, s3, t3 >> 2);

        a0 += fmaxf(v0.x + b0, 0.f) + fmaxf(v0.y + b0, 0.f)
            + fmaxf(v0.z + b0, 0.f) + fmaxf(v0.w + b0, 0.f);
        a1 += fmaxf(v1.x + b1, 0.f) + fmaxf(v1.y + b1, 0.f)
            + fmaxf(v1.z + b1, 0.f) + fmaxf(v1.w + b1, 0.f);
        a2 += fmaxf(v2.x + b2, 0.f) + fmaxf(v2.y + b2, 0.f)
            + fmaxf(v2.z + b2, 0.f) + fmaxf(v2.w + b2, 0.f);
        a3 += fmaxf(v3.x + b3, 0.f) + fmaxf(v3.y + b3, 0.f)
            + fmaxf(v3.z + b3, 0.f) + fmaxf(v3.w + b3, 0.f);
    }

    // Tail (none for the benchmark shape; kept for generality).
    for (; r < rows; r++) {
        const int tgt = is64 ? (int)t64[r] : t32[r];
        const float* p = x + (size_t)r * 128;
        const float4 v = reinterpret_cast<const float4*>(p)[lane];
        float s = (tgt & 2) ? ((tgt & 1) ? v.w : v.z) : ((tgt & 1) ? v.y : v.x);
        const float b = 0.5f - __shfl_sync(0xFFFFFFFFu, s, tgt >> 2);
        a0 += fmaxf(v.x + b, 0.f) + fmaxf(v.y + b, 0.f)
            + fmaxf(v.z + b, 0.f) + fmaxf(v.w + b, 0.f);
    }

    // Lane partials -> warp -> block.
    double d = (double)a0 + (double)a1 + (double)a2 + (double)a3;
    #pragma unroll
    for (int o = 16; o > 0; o >>= 1)
        d += __shfl_xor_sync(0xFFFFFFFFu, d, o);

    __shared__ double ws[8];
    if (lane == 0) ws[wid] = d;
    __syncthreads();

    __shared__ bool s_last;
    if (tid == 0) {
        double b = 0.0;
        #pragma unroll
        for (int i = 0; i < 8; i++) b += ws[i];
        g_part[blockIdx.x] = b;
        __threadfence();
        unsigned t = atomicAdd(&g_ticket, 1u);
        s_last = (t == (unsigned)gridDim.x - 1u);
    }
    __syncthreads();

    // ---- closing block: reduce all partials, finish, reset ticket ----
    if (s_last) {
        double s = 0.0;
        for (int i = tid; i < NBLOCKS; i += 256) s += g_part[i];
        #pragma unroll
        for (int o = 16; o > 0; o >>= 1)
            s += __shfl_xor_sync(0xFFFFFFFFu, s, o);
        if (lane == 0) ws[wid] = s;
        __syncthreads();
        if (tid == 0) {
            double b = 0.0;
            #pragma unroll
            for (int i = 0; i < 8; i++) b += ws[i];
            // Each row's target position contributed exactly max(0, 0.5) = 0.5.
            out[0] = (float)((b - 0.5 * (double)rows) * inv_cnt);
            g_ticket = 0;   // reset for the next (graph-replayed) call
        }
    }
}

extern "C" void kernel_launch(void* const* d_in, const int* in_sizes, int n_in,
                              void* d_out, int out_size)
{
    const float* x      = (const float*)d_in[0];   // [V, C, T] fp32
    const void*  target = d_in[1];                 // [V, C] int32 or int64 (auto-detected)
    float*       out    = (float*)d_out;

    const int T    = 128;
    const int rows = in_sizes[0] / T;              // V*C
    const double cnt = (double)rows * (double)(T - 1);

    mrl_fused_kernel<<<NBLOCKS, 256>>>(x, target, rows, 1.0 / cnt, out);
}